// round 6
// baseline (speedup 1.0000x reference)
#include <cuda_runtime.h>
#include <math.h>

#define SB   2
#define SEQ  256
#define IND  80
#define HID  128
#define G4   512
#define F2D  256
#define NCLS 40
#define WSEG 64
#define HS   100

// ---------------- device scratch ----------------
__device__ float    d_pre [2*SEQ*SB*G4];   // [dir][s][b][512]
__device__ float    d_hbuf[2*2*SB*HID];    // [dir][parity][b][128]
__device__ unsigned d_flag[2];             // per-direction step counters
__device__ float    d_rnn1[SB*SEQ*F2D];
__device__ float    d_rnn2[SB*SEQ*F2D];
__device__ float    d_cum [SB*SEQ*F2D];
__device__ float    d_pd  [SB*SEQ*HS];
__device__ float    d_pe  [SB*SEQ*HS];
__device__ float    d_band[SB*SEQ*WSEG];   // band[b][i][w], j = max(0,i-64)+w

__device__ __forceinline__ unsigned ld_acq(const unsigned* p) {
    unsigned v;
    asm volatile("ld.acquire.gpu.global.u32 %0, [%1];" : "=r"(v) : "l"(p) : "memory");
    return v;
}
__device__ __forceinline__ void red_rel_add1(unsigned* p) {
    asm volatile("red.release.gpu.global.add.u32 [%0], 1;" :: "l"(p) : "memory");
}
__device__ __forceinline__ float preluf(float x, float a) { return x >= 0.f ? x : a * x; }
__device__ __forceinline__ float sigmf(float x) { return 1.f / (1.f + expf(-x)); }

// ---------------- reset flags + h init buffers ----------------
__global__ void reset_kernel() {
    int t = threadIdx.x;
    if (t < 2) d_flag[t] = 0u;
    for (int n = t; n < 2*2*SB*HID; n += blockDim.x) d_hbuf[n] = 0.f;
}

// ---------------- input projection: pre = x @ Wih^T + b ----------------
// grid (S/2, 2 dirs), block 512 (one thread per gate row)
__global__ __launch_bounds__(512) void proj_kernel(
    const float* __restrict__ xin, int K, int use_r1,
    const float* __restrict__ wF, const float* __restrict__ bF,
    const float* __restrict__ wB, const float* __restrict__ bB)
{
    __shared__ float xsh[SB][2][F2D];
    const float* src = use_r1 ? d_rnn1 : xin;
    int dir = blockIdx.y;
    int s0  = blockIdx.x * 2;
    int t   = threadIdx.x;
    for (int n = t; n < SB * 2 * K; n += 512) {
        int b = n / (2 * K); int rem = n % (2 * K);
        int sl = rem / K;    int k = rem % K;
        xsh[b][sl][k] = src[(b * SEQ + s0 + sl) * K + k];
    }
    __syncthreads();
    const float* w = (dir ? wB : wF) + t * K;
    float bias = (dir ? bB : bF)[t];
    float a00 = bias, a01 = bias, a10 = bias, a11 = bias;
    const float4* w4 = (const float4*)w;
    int K4 = K >> 2;
    for (int k4 = 0; k4 < K4; k4++) {
        float4 wv = w4[k4]; int k = k4 * 4;
        a00 += wv.x*xsh[0][0][k] + wv.y*xsh[0][0][k+1] + wv.z*xsh[0][0][k+2] + wv.w*xsh[0][0][k+3];
        a01 += wv.x*xsh[0][1][k] + wv.y*xsh[0][1][k+1] + wv.z*xsh[0][1][k+2] + wv.w*xsh[0][1][k+3];
        a10 += wv.x*xsh[1][0][k] + wv.y*xsh[1][0][k+1] + wv.z*xsh[1][0][k+2] + wv.w*xsh[1][0][k+3];
        a11 += wv.x*xsh[1][1][k] + wv.y*xsh[1][1][k+1] + wv.z*xsh[1][1][k+2] + wv.w*xsh[1][1][k+3];
    }
    d_pre[((dir*SEQ + s0    ) * SB + 0) * G4 + t] = a00;
    d_pre[((dir*SEQ + s0    ) * SB + 1) * G4 + t] = a10;
    d_pre[((dir*SEQ + s0 + 1) * SB + 0) * G4 + t] = a01;
    d_pre[((dir*SEQ + s0 + 1) * SB + 1) * G4 + t] = a11;
}

// ---------------- LSTM recurrence: 4 CTAs per direction, grid 8 ----------------
// CTA cr owns h indices j in [32cr, 32cr+32) (all 4 gates -> 128 rows).
// Thread t: rl=t>>1 row-local, half=t&1 owns 64 of the 128 k's (weights in regs).
__global__ __launch_bounds__(256, 1) void lstm_kernel(
    const float* __restrict__ whhF, const float* __restrict__ whhB, int out_is_l2)
{
    float* out = out_is_l2 ? d_rnn2 : d_rnn1;
    int blk = blockIdx.x, dir = blk >> 2, cr = blk & 3;
    const float* whh = dir ? whhB : whhF;
    int t = threadIdx.x;
    int rl = t >> 1, half = t & 1, gate = rl >> 5, jj = rl & 31;
    int g = gate * HID + cr * 32 + jj;

    float w[64];
    const float4* wr = (const float4*)(whh + g * HID + half * 64);
#pragma unroll
    for (int q = 0; q < 16; q++) {
        float4 v = wr[q];
        w[4*q] = v.x; w[4*q+1] = v.y; w[4*q+2] = v.z; w[4*q+3] = v.w;
    }

    __shared__ float hsm[SB * HID];
    __shared__ float gsm[SB][4][32];
    float c = 0.f;
    int cb = t >> 5, cj = cr * 32 + (t & 31);   // cell mapping for t<64
    unsigned* flag = &d_flag[dir];

    for (int ts = 0; ts < SEQ; ts++) {
        int s = dir ? (SEQ - 1 - ts) : ts;
        int rp = (ts + 1) & 1, wp = ts & 1;
        float pre0 = d_pre[((dir*SEQ + s) * SB + 0) * G4 + g];
        float pre1 = d_pre[((dir*SEQ + s) * SB + 1) * G4 + g];
        if (ts > 0 && t == 0) {
            while (ld_acq(flag) < (unsigned)(4 * ts)) { }
        }
        __syncthreads();
        hsm[t] = d_hbuf[(dir * 2 + rp) * SB * HID + t];
        __syncthreads();

        const float4* h0 = (const float4*)&hsm[0 * HID + half * 64];
        const float4* h1 = (const float4*)&hsm[1 * HID + half * 64];
        float a0 = 0.f, a1 = 0.f;
#pragma unroll
        for (int q = 0; q < 16; q++) {
            float4 v0 = h0[q], v1 = h1[q];
            a0 += w[4*q]*v0.x + w[4*q+1]*v0.y + w[4*q+2]*v0.z + w[4*q+3]*v0.w;
            a1 += w[4*q]*v1.x + w[4*q+1]*v1.y + w[4*q+2]*v1.z + w[4*q+3]*v1.w;
        }
        a0 += __shfl_xor_sync(0xffffffffu, a0, 1);
        a1 += __shfl_xor_sync(0xffffffffu, a1, 1);
        if (half == 0) {
            gsm[0][gate][jj] = pre0 + a0;
            gsm[1][gate][jj] = pre1 + a1;
        }
        __syncthreads();
        if (t < 64) {
            int jl = t & 31;
            float gi = gsm[cb][0][jl], gf = gsm[cb][1][jl];
            float gg = gsm[cb][2][jl], go = gsm[cb][3][jl];
            c = sigmf(gf) * c + sigmf(gi) * tanhf(gg);
            float h = sigmf(go) * tanhf(c);
            d_hbuf[(dir * 2 + wp) * SB * HID + cb * HID + cj] = h;
            out[(cb * SEQ + s) * F2D + dir * HID + cj] = h;
            __threadfence();
        }
        __syncthreads();
        if (t == 0) red_rel_add1(flag);
    }
}

// ---------------- inclusive cumsum over s ----------------
__global__ void cumsum_kernel() {
    int b = blockIdx.x, k = threadIdx.x;
    float acc = 0.f;
    for (int s = 0; s < SEQ; s++) {
        acc += d_rnn2[(b * SEQ + s) * F2D + k];
        d_cum[(b * SEQ + s) * F2D + k] = acc;
    }
}

// ---------------- per-position d/e parts of score MLP layer 1 ----------------
__global__ __launch_bounds__(128) void pdpe_kernel(
    const float* __restrict__ w1, const float* __restrict__ b1,
    const float* __restrict__ a0p)
{
    int b = blockIdx.x >> 8, s = blockIdx.x & 255, t = threadIdx.x;
    float a0 = *a0p;
    __shared__ float px[F2D];
    for (int k = t; k < F2D; k += 128) px[k] = preluf(d_rnn2[(b * SEQ + s) * F2D + k], a0);
    __syncthreads();
    if (t < HS) {
        const float4* wd = (const float4*)(w1 + t * 768 + 256);
        const float4* we = (const float4*)(w1 + t * 768 + 512);
        float ad = 0.f, ae = 0.f;
        for (int k4 = 0; k4 < 64; k4++) {
            float4 v = wd[k4], u = we[k4]; int k = k4 * 4;
            ad += v.x*px[k] + v.y*px[k+1] + v.z*px[k+2] + v.w*px[k+3];
            ae += u.x*px[k] + u.y*px[k+1] + u.z*px[k+2] + u.w*px[k+3];
        }
        d_pd[(b * SEQ + s) * HS + t] = ad;
        d_pe[(b * SEQ + s) * HS + t] = ae + b1[t];
    }
}

// ---------------- cls + bin MLPs ----------------
__global__ __launch_bounds__(160) void clsbin_kernel(
    const float* a_c0, const float* w_c1, const float* b_c1,
    const float* a_c1, const float* w_c2, const float* b_c2,
    const float* a_b0, const float* w_b1, const float* b_b1,
    const float* a_b1, const float* w_b2, const float* b_b2,
    float* __restrict__ out)
{
    int b = blockIdx.x >> 8, s = blockIdx.x & 255, t = threadIdx.x;
    __shared__ float xr[F2D];
    __shared__ float hc[80], hb[80];
    for (int k = t; k < F2D; k += 160) xr[k] = d_rnn2[(b * SEQ + s) * F2D + k];
    __syncthreads();
    {
        int row = t % 80;
        bool isb = t >= 80;
        const float* wrow = (isb ? w_b1 : w_c1) + row * F2D;
        float alpha = isb ? *a_b0 : *a_c0;
        float acc = (isb ? b_b1 : b_c1)[row];
        for (int k = 0; k < F2D; k++) acc += wrow[k] * preluf(xr[k], alpha);
        if (isb) hb[row] = acc; else hc[row] = acc;
    }
    __syncthreads();
    if (t < NCLS) {
        float a1 = *a_c1, acc = b_c2[t];
        for (int q = 0; q < 80; q++) acc += w_c2[t * 80 + q] * preluf(hc[q], a1);
        out[(b * SEQ + s) * NCLS + t] = acc;
    } else if (t < NCLS + 2) {
        int r = t - NCLS;
        float a1 = *a_b1, acc = b_b2[r];
        for (int q = 0; q < 80; q++) acc += w_b2[r * 80 + q] * preluf(hb[q], a1);
        out[SB*SEQ*NCLS + (b * SEQ + s) * 2 + r] = acc;
    }
}

// ---------------- banded pairwise scores ----------------
// grid 510: b = bid&1, i = 1 + (bid>>1). smem: phi(64 x 256 padded) + W1c(112 x 256 padded)
#define RPAD 65   // float4 row stride (260 floats) -> 2-way bank conflicts only
__global__ __launch_bounds__(256) void band_kernel(
    const float* __restrict__ w1, const float* __restrict__ w2,
    const float* __restrict__ b2, const float* __restrict__ a0p,
    const float* __restrict__ a1p)
{
    extern __shared__ float smraw[];
    float4* phi = (float4*)smraw;
    float4* w1s = phi + 64 * RPAD;
    int b = blockIdx.x & 1;
    int i = 1 + (blockIdx.x >> 1);
    int start = i > WSEG ? i - WSEG : 0;
    int t = threadIdx.x;
    float a0 = *a0p;

    for (int n = t; n < 112 * 64; n += 256) {           // stage W1 cols [0,256)
        int r = n >> 6, k4 = n & 63;
        float4 v = make_float4(0.f, 0.f, 0.f, 0.f);
        if (r < HS) v = ((const float4*)(w1 + r * 768))[k4];
        w1s[r * RPAD + k4] = v;
    }
    const float4* cum4 = (const float4*)d_cum;
    for (int n = t; n < 64 * 64; n += 256) {            // phi = prelu(cum_i - cum_j)
        int wdx = n >> 6, k4 = n & 63;
        int j = start + wdx;
        float4 ci = cum4[(b * SEQ + i) * 64 + k4];
        float4 cj = cum4[(b * SEQ + j) * 64 + k4];
        float4 d;
        d.x = preluf(ci.x - cj.x, a0); d.y = preluf(ci.y - cj.y, a0);
        d.z = preluf(ci.z - cj.z, a0); d.w = preluf(ci.w - cj.w, a0);
        phi[wdx * RPAD + k4] = d;
    }
    __syncthreads();

    int tw = t & 15, tr = t >> 4;
    float acc[4][7];
#pragma unroll
    for (int q = 0; q < 4; q++)
#pragma unroll
        for (int p = 0; p < 7; p++) acc[q][p] = 0.f;

    for (int k4 = 0; k4 < 64; k4++) {
        float4 ph[4];
#pragma unroll
        for (int q = 0; q < 4; q++) ph[q] = phi[(tr + 16 * q) * RPAD + k4];
#pragma unroll
        for (int p = 0; p < 7; p++) {
            float4 wv = w1s[(tw + 16 * p) * RPAD + k4];
#pragma unroll
            for (int q = 0; q < 4; q++)
                acc[q][p] += ph[q].x*wv.x + ph[q].y*wv.y + ph[q].z*wv.z + ph[q].w*wv.w;
        }
    }

    float a1 = *a1p;
    float loc[4] = {0.f, 0.f, 0.f, 0.f};
#pragma unroll
    for (int p = 0; p < 7; p++) {
        int r = tw + 16 * p;
        float w2v = (r < HS) ? w2[r] : 0.f;
        float pev = (r < HS) ? d_pe[(b * SEQ + i) * HS + r] : 0.f;
#pragma unroll
        for (int q = 0; q < 4; q++) {
            int j = start + tr + 16 * q;
            float pdv = (r < HS) ? d_pd[(b * SEQ + j) * HS + r] : 0.f;
            float h = acc[q][p] + pdv + pev;
            loc[q] += preluf(h, a1) * w2v;
        }
    }
#pragma unroll
    for (int off = 8; off >= 1; off >>= 1)
#pragma unroll
        for (int q = 0; q < 4; q++)
            loc[q] += __shfl_xor_sync(0xffffffffu, loc[q], off, 16);
    if (tw == 0) {
        float bb = b2[0];
#pragma unroll
        for (int q = 0; q < 4; q++)
            d_band[(b * SEQ + i) * WSEG + tr + 16 * q] = loc[q] + bb;
    }
}

// ---------------- DP + backtrack (single CTA, band in smem) ----------------
__global__ __launch_bounds__(256) void dp_kernel(const int* __restrict__ lengths,
                                                 float* __restrict__ out)
{
    extern __shared__ float bs[];               // 2*256*64 floats
    __shared__ float best[SB][SEQ];
    __shared__ int   bp[SB][SEQ];
    int t = threadIdx.x;
    const float4* src = (const float4*)d_band;
    float4* dst = (float4*)bs;
    for (int n = t; n < SB * SEQ * WSEG / 4; n += 256) dst[n] = src[n];
    float* bm = out + SB*SEQ*NCLS + SB*SEQ*2;
    for (int n = t; n < SB * SEQ; n += 256) bm[n] = 0.f;
    if (t < SB) { best[t][0] = 0.f; bp[t][0] = 0; }
    __syncthreads();

    if (t < 64) {
        int b = t >> 5, l = t & 31;
        for (int i = 1; i < SEQ; i++) {
            int start = i > WSEG ? i - WSEG : 0;
            const float* row = &bs[(b * SEQ + i) * WSEG];
            int j1 = start + l;
            float v1 = (j1 < i) ? best[b][j1] + row[l] : -1e9f;
            int j2 = start + l + 32;
            float v2 = (j2 < i) ? best[b][j2] + row[l + 32] : -1e9f;
            float v; int wj;
            if (v2 > v1) { v = v2; wj = j2; } else { v = v1; wj = j1; }
#pragma unroll
            for (int off = 16; off >= 1; off >>= 1) {
                float ov = __shfl_xor_sync(0xffffffffu, v, off);
                int   oj = __shfl_xor_sync(0xffffffffu, wj, off);
                if (ov > v || (ov == v && oj < wj)) { v = ov; wj = oj; }
            }
            if (l == 0) { best[b][i] = v; bp[b][i] = wj; }
            __syncwarp();
        }
    }
    __syncthreads();
    if (t == 0 || t == 32) {
        int b = t >> 5;
        int cur = lengths[b] - 1;
        float acc = 0.f;
        while (true) {
            bm[b * SEQ + cur] = 1.f;
            if (cur == 0) break;
            int prev = bp[b][cur];
            int start = cur > WSEG ? cur - WSEG : 0;
            acc += bs[(b * SEQ + cur) * WSEG + (prev - start)];
            cur = prev;
        }
        out[SB*SEQ*NCLS + SB*SEQ*2 + SB*SEQ + b] = acc;
    }
}

// ---------------- launch ----------------
extern "C" void kernel_launch(void* const* d_in, const int* in_sizes, int n_in,
                              void* d_out, int out_size)
{
    const float* x      = (const float*)d_in[0];
    const int*   lens   = (const int*)  d_in[1];
    const float* wih0f  = (const float*)d_in[2];
    const float* whh0f  = (const float*)d_in[3];
    const float* b0f    = (const float*)d_in[4];
    const float* wih0b  = (const float*)d_in[5];
    const float* whh0b  = (const float*)d_in[6];
    const float* b0b    = (const float*)d_in[7];
    const float* wih1f  = (const float*)d_in[8];
    const float* whh1f  = (const float*)d_in[9];
    const float* b1f    = (const float*)d_in[10];
    const float* wih1b  = (const float*)d_in[11];
    const float* whh1b  = (const float*)d_in[12];
    const float* b1b    = (const float*)d_in[13];
    const float* a_s0   = (const float*)d_in[14];
    const float* w_s1   = (const float*)d_in[15];
    const float* b_s1   = (const float*)d_in[16];
    const float* a_s1   = (const float*)d_in[17];
    const float* w_s2   = (const float*)d_in[18];
    const float* b_s2   = (const float*)d_in[19];
    const float* a_c0   = (const float*)d_in[20];
    const float* w_c1   = (const float*)d_in[21];
    const float* b_c1   = (const float*)d_in[22];
    const float* a_c1   = (const float*)d_in[23];
    const float* w_c2   = (const float*)d_in[24];
    const float* b_c2   = (const float*)d_in[25];
    const float* a_b0   = (const float*)d_in[26];
    const float* w_b1   = (const float*)d_in[27];
    const float* b_b1   = (const float*)d_in[28];
    const float* a_b1   = (const float*)d_in[29];
    const float* w_b2   = (const float*)d_in[30];
    const float* b_b2   = (const float*)d_in[31];
    float* out = (float*)d_out;

    cudaFuncSetAttribute(band_kernel, cudaFuncAttributeMaxDynamicSharedMemorySize, 183040);
    cudaFuncSetAttribute(dp_kernel,   cudaFuncAttributeMaxDynamicSharedMemorySize, 131072);

    reset_kernel<<<1, 256>>>();
    proj_kernel<<<dim3(128, 2), 512>>>(x, IND, 0, wih0f, b0f, wih0b, b0b);
    lstm_kernel<<<8, 256>>>(whh0f, whh0b, 0);
    reset_kernel<<<1, 256>>>();
    proj_kernel<<<dim3(128, 2), 512>>>(x, F2D, 1, wih1f, b1f, wih1b, b1b);
    lstm_kernel<<<8, 256>>>(whh1f, whh1b, 1);
    cumsum_kernel<<<2, 256>>>();
    pdpe_kernel<<<512, 128>>>(w_s1, b_s1, a_s0);
    clsbin_kernel<<<512, 160>>>(a_c0, w_c1, b_c1, a_c1, w_c2, b_c2,
                                a_b0, w_b1, b_b1, a_b1, w_b2, b_b2, out);
    band_kernel<<<510, 256, 183040>>>(w_s1, w_s2, b_s2, a_s0, a_s1);
    dp_kernel<<<1, 256, 131072>>>(lens, out);
}

// round 8
// speedup vs baseline: 1.3963x; 1.3963x over previous
#include <cuda_runtime.h>
#include <cooperative_groups.h>
#include <math.h>

namespace cg = cooperative_groups;

#define SB   2
#define SEQ  256
#define IND  80
#define HID  128
#define G4   512
#define F2D  256
#define NCLS 40
#define WSEG 64
#define HS   100

// ---------------- device scratch ----------------
__device__ float    d_pre [2*SEQ*SB*G4];   // [dir][s][b][512]
__device__ float    d_rnn1[SB*SEQ*F2D];
__device__ float    d_rnn2[SB*SEQ*F2D];
__device__ float    d_cum [SB*SEQ*F2D];
__device__ float    d_pd  [SB*SEQ*HS];
__device__ float    d_pe  [SB*SEQ*HS];
__device__ float    d_band[SB*SEQ*WSEG];   // band[b][i][w], j = max(0,i-64)+w

__device__ __forceinline__ float preluf(float x, float a) { return x >= 0.f ? x : a * x; }
__device__ __forceinline__ float sigmf(float x) { return 1.f / (1.f + expf(-x)); }

// ---------------- input projection: pre = x @ Wih^T + b ----------------
// grid (S/2, 2 dirs), block 512 (one thread per gate row)
__global__ __launch_bounds__(512) void proj_kernel(
    const float* __restrict__ xin, int K, int use_r1,
    const float* __restrict__ wF, const float* __restrict__ bF,
    const float* __restrict__ wB, const float* __restrict__ bB)
{
    __shared__ float xsh[SB][2][F2D];
    const float* src = use_r1 ? d_rnn1 : xin;
    int dir = blockIdx.y;
    int s0  = blockIdx.x * 2;
    int t   = threadIdx.x;
    for (int n = t; n < SB * 2 * K; n += 512) {
        int b = n / (2 * K); int rem = n % (2 * K);
        int sl = rem / K;    int k = rem % K;
        xsh[b][sl][k] = src[(b * SEQ + s0 + sl) * K + k];
    }
    __syncthreads();
    const float* w = (dir ? wB : wF) + t * K;
    float bias = (dir ? bB : bF)[t];
    float a00 = bias, a01 = bias, a10 = bias, a11 = bias;
    const float4* w4 = (const float4*)w;
    int K4 = K >> 2;
    for (int k4 = 0; k4 < K4; k4++) {
        float4 wv = w4[k4]; int k = k4 * 4;
        a00 += wv.x*xsh[0][0][k] + wv.y*xsh[0][0][k+1] + wv.z*xsh[0][0][k+2] + wv.w*xsh[0][0][k+3];
        a01 += wv.x*xsh[0][1][k] + wv.y*xsh[0][1][k+1] + wv.z*xsh[0][1][k+2] + wv.w*xsh[0][1][k+3];
        a10 += wv.x*xsh[1][0][k] + wv.y*xsh[1][0][k+1] + wv.z*xsh[1][0][k+2] + wv.w*xsh[1][0][k+3];
        a11 += wv.x*xsh[1][1][k] + wv.y*xsh[1][1][k+1] + wv.z*xsh[1][1][k+2] + wv.w*xsh[1][1][k+3];
    }
    d_pre[((dir*SEQ + s0    ) * SB + 0) * G4 + t] = a00;
    d_pre[((dir*SEQ + s0    ) * SB + 1) * G4 + t] = a10;
    d_pre[((dir*SEQ + s0 + 1) * SB + 0) * G4 + t] = a01;
    d_pre[((dir*SEQ + s0 + 1) * SB + 1) * G4 + t] = a11;
}

// ---------------- LSTM recurrence: one 4-CTA cluster per direction ----------------
// grid 8 = 2 clusters of 4. CTA cr owns h indices j in [32cr, 32cr+32) (x4 gates).
// Thread t: rl=t>>1 row-local, half=t&1 owns 64 of the 128 k's (weights in regs).
// h is exchanged via DSMEM writes into every cluster CTA's smem + cluster.sync.
__global__ __launch_bounds__(256, 1) __cluster_dims__(4, 1, 1)
void lstm_kernel(const float* __restrict__ whhF, const float* __restrict__ whhB,
                 int out_is_l2)
{
    cg::cluster_group cluster = cg::this_cluster();
    float* out = out_is_l2 ? d_rnn2 : d_rnn1;
    int blk = blockIdx.x, dir = blk >> 2, cr = blk & 3;
    const float* whh = dir ? whhB : whhF;
    int t = threadIdx.x;
    int rl = t >> 1, half = t & 1, gate = rl >> 5, jj = rl & 31;
    int g = gate * HID + cr * 32 + jj;

    float w[64];
    const float4* wr = (const float4*)(whh + g * HID + half * 64);
#pragma unroll
    for (int q = 0; q < 16; q++) {
        float4 v = wr[q];
        w[4*q] = v.x; w[4*q+1] = v.y; w[4*q+2] = v.z; w[4*q+3] = v.w;
    }

    __shared__ float hsm[2][SB * HID];     // double-buffered h, full 256 vector
    __shared__ float gsm[SB][4][32];
    float c = 0.f;
    int cb = t >> 5, cjl = t & 31;         // cell mapping for t<64
    int cj = cr * 32 + cjl;

    hsm[0][t] = 0.f;                       // ts=0 reads buffer 0

    // peer smem base pointers (same layout in every CTA of the cluster)
    float* peer[4];
#pragma unroll
    for (int r = 0; r < 4; r++) peer[r] = cluster.map_shared_rank(&hsm[0][0], r);

    cluster.sync();                        // init visible; peers resident

    for (int ts = 0; ts < SEQ; ts++) {
        int s = dir ? (SEQ - 1 - ts) : ts;
        int rb = ts & 1, wb = rb ^ 1;
        float pre0 = d_pre[((dir*SEQ + s) * SB + 0) * G4 + g];
        float pre1 = d_pre[((dir*SEQ + s) * SB + 1) * G4 + g];

        const float4* h0 = (const float4*)&hsm[rb][0 * HID + half * 64];
        const float4* h1 = (const float4*)&hsm[rb][1 * HID + half * 64];
        float a0 = 0.f, a1 = 0.f;
#pragma unroll
        for (int q = 0; q < 16; q++) {
            float4 v0 = h0[q], v1 = h1[q];
            a0 += w[4*q]*v0.x + w[4*q+1]*v0.y + w[4*q+2]*v0.z + w[4*q+3]*v0.w;
            a1 += w[4*q]*v1.x + w[4*q+1]*v1.y + w[4*q+2]*v1.z + w[4*q+3]*v1.w;
        }
        a0 += __shfl_xor_sync(0xffffffffu, a0, 1);
        a1 += __shfl_xor_sync(0xffffffffu, a1, 1);
        if (half == 0) {
            gsm[0][gate][jj] = pre0 + a0;
            gsm[1][gate][jj] = pre1 + a1;
        }
        __syncthreads();
        if (t < 64) {
            float gi = gsm[cb][0][cjl], gf = gsm[cb][1][cjl];
            float gg = gsm[cb][2][cjl], go = gsm[cb][3][cjl];
            c = sigmf(gf) * c + sigmf(gi) * tanhf(gg);
            float h = sigmf(go) * tanhf(c);
            int off = wb * (SB * HID) + cb * HID + cj;
#pragma unroll
            for (int r = 0; r < 4; r++) peer[r][off] = h;   // DSMEM broadcast
            out[(cb * SEQ + s) * F2D + dir * HID + cj] = h;
        }
        cluster.sync();   // release h writes; all CTAs done with rb/gsm
    }
}

// ---------------- inclusive cumsum over s ----------------
__global__ void cumsum_kernel() {
    int b = blockIdx.x, k = threadIdx.x;
    float acc = 0.f;
    for (int s = 0; s < SEQ; s++) {
        acc += d_rnn2[(b * SEQ + s) * F2D + k];
        d_cum[(b * SEQ + s) * F2D + k] = acc;
    }
}

// ---------------- per-position d/e parts of score MLP layer 1 ----------------
__global__ __launch_bounds__(128) void pdpe_kernel(
    const float* __restrict__ w1, const float* __restrict__ b1,
    const float* __restrict__ a0p)
{
    int b = blockIdx.x >> 8, s = blockIdx.x & 255, t = threadIdx.x;
    float a0 = *a0p;
    __shared__ float px[F2D];
    for (int k = t; k < F2D; k += 128) px[k] = preluf(d_rnn2[(b * SEQ + s) * F2D + k], a0);
    __syncthreads();
    if (t < HS) {
        const float4* wd = (const float4*)(w1 + t * 768 + 256);
        const float4* we = (const float4*)(w1 + t * 768 + 512);
        float ad = 0.f, ae = 0.f;
        for (int k4 = 0; k4 < 64; k4++) {
            float4 v = wd[k4], u = we[k4]; int k = k4 * 4;
            ad += v.x*px[k] + v.y*px[k+1] + v.z*px[k+2] + v.w*px[k+3];
            ae += u.x*px[k] + u.y*px[k+1] + u.z*px[k+2] + u.w*px[k+3];
        }
        d_pd[(b * SEQ + s) * HS + t] = ad;
        d_pe[(b * SEQ + s) * HS + t] = ae + b1[t];
    }
}

// ---------------- cls + bin MLPs ----------------
__global__ __launch_bounds__(160) void clsbin_kernel(
    const float* a_c0, const float* w_c1, const float* b_c1,
    const float* a_c1, const float* w_c2, const float* b_c2,
    const float* a_b0, const float* w_b1, const float* b_b1,
    const float* a_b1, const float* w_b2, const float* b_b2,
    float* __restrict__ out)
{
    int b = blockIdx.x >> 8, s = blockIdx.x & 255, t = threadIdx.x;
    __shared__ float xr[F2D];
    __shared__ float hc[80], hb[80];
    for (int k = t; k < F2D; k += 160) xr[k] = d_rnn2[(b * SEQ + s) * F2D + k];
    __syncthreads();
    {
        int row = t % 80;
        bool isb = t >= 80;
        const float* wrow = (isb ? w_b1 : w_c1) + row * F2D;
        float alpha = isb ? *a_b0 : *a_c0;
        float acc = (isb ? b_b1 : b_c1)[row];
        for (int k = 0; k < F2D; k++) acc += wrow[k] * preluf(xr[k], alpha);
        if (isb) hb[row] = acc; else hc[row] = acc;
    }
    __syncthreads();
    if (t < NCLS) {
        float a1 = *a_c1, acc = b_c2[t];
        for (int q = 0; q < 80; q++) acc += w_c2[t * 80 + q] * preluf(hc[q], a1);
        out[(b * SEQ + s) * NCLS + t] = acc;
    } else if (t < NCLS + 2) {
        int r = t - NCLS;
        float a1 = *a_b1, acc = b_b2[r];
        for (int q = 0; q < 80; q++) acc += w_b2[r * 80 + q] * preluf(hb[q], a1);
        out[SB*SEQ*NCLS + (b * SEQ + s) * 2 + r] = acc;
    }
}

// ---------------- banded pairwise scores ----------------
// grid 510: b = bid&1, i = 1 + (bid>>1). smem: phi(64 x 256 padded) + W1c(112 x 256 padded)
#define RPAD 65   // float4 row stride (260 floats) -> 2-way bank conflicts only
__global__ __launch_bounds__(256) void band_kernel(
    const float* __restrict__ w1, const float* __restrict__ w2,
    const float* __restrict__ b2, const float* __restrict__ a0p,
    const float* __restrict__ a1p)
{
    extern __shared__ float smraw[];
    float4* phi = (float4*)smraw;
    float4* w1s = phi + 64 * RPAD;
    int b = blockIdx.x & 1;
    int i = 1 + (blockIdx.x >> 1);
    int start = i > WSEG ? i - WSEG : 0;
    int t = threadIdx.x;
    float a0 = *a0p;

    for (int n = t; n < 112 * 64; n += 256) {           // stage W1 cols [0,256)
        int r = n >> 6, k4 = n & 63;
        float4 v = make_float4(0.f, 0.f, 0.f, 0.f);
        if (r < HS) v = ((const float4*)(w1 + r * 768))[k4];
        w1s[r * RPAD + k4] = v;
    }
    const float4* cum4 = (const float4*)d_cum;
    for (int n = t; n < 64 * 64; n += 256) {            // phi = prelu(cum_i - cum_j)
        int wdx = n >> 6, k4 = n & 63;
        int j = start + wdx;
        float4 ci = cum4[(b * SEQ + i) * 64 + k4];
        float4 cj = cum4[(b * SEQ + j) * 64 + k4];
        float4 d;
        d.x = preluf(ci.x - cj.x, a0); d.y = preluf(ci.y - cj.y, a0);
        d.z = preluf(ci.z - cj.z, a0); d.w = preluf(ci.w - cj.w, a0);
        phi[wdx * RPAD + k4] = d;
    }
    __syncthreads();

    int tw = t & 15, tr = t >> 4;
    float acc[4][7];
#pragma unroll
    for (int q = 0; q < 4; q++)
#pragma unroll
        for (int p = 0; p < 7; p++) acc[q][p] = 0.f;

    for (int k4 = 0; k4 < 64; k4++) {
        float4 ph[4];
#pragma unroll
        for (int q = 0; q < 4; q++) ph[q] = phi[(tr + 16 * q) * RPAD + k4];
#pragma unroll
        for (int p = 0; p < 7; p++) {
            float4 wv = w1s[(tw + 16 * p) * RPAD + k4];
#pragma unroll
            for (int q = 0; q < 4; q++)
                acc[q][p] += ph[q].x*wv.x + ph[q].y*wv.y + ph[q].z*wv.z + ph[q].w*wv.w;
        }
    }

    float a1 = *a1p;
    float loc[4] = {0.f, 0.f, 0.f, 0.f};
#pragma unroll
    for (int p = 0; p < 7; p++) {
        int r = tw + 16 * p;
        float w2v = (r < HS) ? w2[r] : 0.f;
        float pev = (r < HS) ? d_pe[(b * SEQ + i) * HS + r] : 0.f;
#pragma unroll
        for (int q = 0; q < 4; q++) {
            int j = start + tr + 16 * q;
            float pdv = (r < HS) ? d_pd[(b * SEQ + j) * HS + r] : 0.f;
            float h = acc[q][p] + pdv + pev;
            loc[q] += preluf(h, a1) * w2v;
        }
    }
#pragma unroll
    for (int off = 8; off >= 1; off >>= 1)
#pragma unroll
        for (int q = 0; q < 4; q++)
            loc[q] += __shfl_xor_sync(0xffffffffu, loc[q], off, 16);
    if (tw == 0) {
        float bb = b2[0];
#pragma unroll
        for (int q = 0; q < 4; q++)
            d_band[(b * SEQ + i) * WSEG + tr + 16 * q] = loc[q] + bb;
    }
}

// ---------------- DP + backtrack (single CTA, band in smem) ----------------
__global__ __launch_bounds__(256) void dp_kernel(const int* __restrict__ lengths,
                                                 float* __restrict__ out)
{
    extern __shared__ float bs[];               // 2*256*64 floats
    __shared__ float best[SB][SEQ];
    __shared__ int   bp[SB][SEQ];
    int t = threadIdx.x;
    const float4* src = (const float4*)d_band;
    float4* dst = (float4*)bs;
    for (int n = t; n < SB * SEQ * WSEG / 4; n += 256) dst[n] = src[n];
    float* bm = out + SB*SEQ*NCLS + SB*SEQ*2;
    for (int n = t; n < SB * SEQ; n += 256) bm[n] = 0.f;
    if (t < SB) { best[t][0] = 0.f; bp[t][0] = 0; }
    __syncthreads();

    if (t < 64) {
        int b = t >> 5, l = t & 31;
        for (int i = 1; i < SEQ; i++) {
            int start = i > WSEG ? i - WSEG : 0;
            const float* row = &bs[(b * SEQ + i) * WSEG];
            int j1 = start + l;
            float v1 = (j1 < i) ? best[b][j1] + row[l] : -1e9f;
            int j2 = start + l + 32;
            float v2 = (j2 < i) ? best[b][j2] + row[l + 32] : -1e9f;
            float v; int wj;
            if (v2 > v1) { v = v2; wj = j2; } else { v = v1; wj = j1; }
#pragma unroll
            for (int off = 16; off >= 1; off >>= 1) {
                float ov = __shfl_xor_sync(0xffffffffu, v, off);
                int   oj = __shfl_xor_sync(0xffffffffu, wj, off);
                if (ov > v || (ov == v && oj < wj)) { v = ov; wj = oj; }
            }
            if (l == 0) { best[b][i] = v; bp[b][i] = wj; }
            __syncwarp();
        }
    }
    __syncthreads();
    if (t == 0 || t == 32) {
        int b = t >> 5;
        int cur = lengths[b] - 1;
        float acc = 0.f;
        while (true) {
            bm[b * SEQ + cur] = 1.f;
            if (cur == 0) break;
            int prev = bp[b][cur];
            int start = cur > WSEG ? cur - WSEG : 0;
            acc += bs[(b * SEQ + cur) * WSEG + (prev - start)];
            cur = prev;
        }
        out[SB*SEQ*NCLS + SB*SEQ*2 + SB*SEQ + b] = acc;
    }
}

// ---------------- launch ----------------
extern "C" void kernel_launch(void* const* d_in, const int* in_sizes, int n_in,
                              void* d_out, int out_size)
{
    const float* x      = (const float*)d_in[0];
    const int*   lens   = (const int*)  d_in[1];
    const float* wih0f  = (const float*)d_in[2];
    const float* whh0f  = (const float*)d_in[3];
    const float* b0f    = (const float*)d_in[4];
    const float* wih0b  = (const float*)d_in[5];
    const float* whh0b  = (const float*)d_in[6];
    const float* b0b    = (const float*)d_in[7];
    const float* wih1f  = (const float*)d_in[8];
    const float* whh1f  = (const float*)d_in[9];
    const float* b1f    = (const float*)d_in[10];
    const float* wih1b  = (const float*)d_in[11];
    const float* whh1b  = (const float*)d_in[12];
    const float* b1b    = (const float*)d_in[13];
    const float* a_s0   = (const float*)d_in[14];
    const float* w_s1   = (const float*)d_in[15];
    const float* b_s1   = (const float*)d_in[16];
    const float* a_s1   = (const float*)d_in[17];
    const float* w_s2   = (const float*)d_in[18];
    const float* b_s2   = (const float*)d_in[19];
    const float* a_c0   = (const float*)d_in[20];
    const float* w_c1   = (const float*)d_in[21];
    const float* b_c1   = (const float*)d_in[22];
    const float* a_c1   = (const float*)d_in[23];
    const float* w_c2   = (const float*)d_in[24];
    const float* b_c2   = (const float*)d_in[25];
    const float* a_b0   = (const float*)d_in[26];
    const float* w_b1   = (const float*)d_in[27];
    const float* b_b1   = (const float*)d_in[28];
    const float* a_b1   = (const float*)d_in[29];
    const float* w_b2   = (const float*)d_in[30];
    const float* b_b2   = (const float*)d_in[31];
    float* out = (float*)d_out;

    cudaFuncSetAttribute(band_kernel, cudaFuncAttributeMaxDynamicSharedMemorySize, 183040);
    cudaFuncSetAttribute(dp_kernel,   cudaFuncAttributeMaxDynamicSharedMemorySize, 131072);

    proj_kernel<<<dim3(128, 2), 512>>>(x, IND, 0, wih0f, b0f, wih0b, b0b);
    lstm_kernel<<<8, 256>>>(whh0f, whh0b, 0);
    proj_kernel<<<dim3(128, 2), 512>>>(x, F2D, 1, wih1f, b1f, wih1b, b1b);
    lstm_kernel<<<8, 256>>>(whh1f, whh1b, 1);
    cumsum_kernel<<<2, 256>>>();
    pdpe_kernel<<<512, 128>>>(w_s1, b_s1, a_s0);
    clsbin_kernel<<<512, 160>>>(a_c0, w_c1, b_c1, a_c1, w_c2, b_c2,
                                a_b0, w_b1, b_b1, a_b1, w_b2, b_b2, out);
    band_kernel<<<510, 256, 183040>>>(w_s1, w_s2, b_s2, a_s0, a_s1);
    dp_kernel<<<1, 256, 131072>>>(lens, out);
}

// round 12
// speedup vs baseline: 1.8049x; 1.2926x over previous
#include <cuda_runtime.h>
#include <cooperative_groups.h>
#include <math.h>

namespace cg = cooperative_groups;

#define SB   2
#define SEQ  256
#define IND  80
#define HID  128
#define G4   512
#define F2D  256
#define NCLS 40
#define WSEG 64
#define HS   100

// ---------------- device scratch ----------------
__device__ float    d_pre [2*SEQ*SB*G4];   // [dir][s][b][512]
__device__ float    d_rnn1[SB*SEQ*F2D];
__device__ float    d_rnn2[SB*SEQ*F2D];
__device__ float    d_cum [SB*SEQ*F2D];
__device__ float    d_pd  [SB*SEQ*HS];
__device__ float    d_pe  [SB*SEQ*HS];
__device__ float    d_band[SB*SEQ*WSEG];   // band[b][i][w], j = max(0,i-64)+w

__device__ __forceinline__ float preluf(float x, float a) { return x >= 0.f ? x : a * x; }
__device__ __forceinline__ float sigmf(float x) { return 1.f / (1.f + expf(-x)); }

__device__ __forceinline__ uint32_t smem_u32(const void* p) {
    uint32_t a;
    asm("{ .reg .u64 t; cvta.to.shared.u64 t, %1; cvt.u32.u64 %0, t; }" : "=r"(a) : "l"(p));
    return a;
}
__device__ __forceinline__ void mbar_init(uint32_t bar, uint32_t cnt) {
    asm volatile("mbarrier.init.shared.b64 [%0], %1;" :: "r"(bar), "r"(cnt) : "memory");
}
// arrive on the mbarrier at the same smem offset in cluster CTA `rank` (release.cluster)
__device__ __forceinline__ void mbar_arrive_rank(uint32_t bar, uint32_t rank) {
    asm volatile(
        "{\n\t.reg .b32 r;\n\t"
        "mapa.shared::cluster.u32 r, %0, %1;\n\t"
        "mbarrier.arrive.shared::cluster.b64 _, [r];\n\t}"
        :: "r"(bar), "r"(rank) : "memory");
}
// wait for phase `parity` completion with cluster-scope acquire
__device__ __forceinline__ void mbar_wait_cluster(uint32_t bar, uint32_t parity) {
    asm volatile(
        "{\n\t.reg .pred P;\n\t"
        "LW%=:\n\t"
        "mbarrier.try_wait.parity.acquire.cluster.shared::cta.b64 P, [%0], %1, 0x989680;\n\t"
        "@P bra LD%=;\n\t"
        "bra LW%=;\n\t"
        "LD%=:\n\t}"
        :: "r"(bar), "r"(parity) : "memory");
}

// ---------------- input projection: pre = x @ Wih^T + b ----------------
// grid (S/2, 2 dirs), block 512 (one thread per gate row)
__global__ __launch_bounds__(512) void proj_kernel(
    const float* __restrict__ xin, int K, int use_r1,
    const float* __restrict__ wF, const float* __restrict__ bF,
    const float* __restrict__ wB, const float* __restrict__ bB)
{
    __shared__ float xsh[SB][2][F2D];
    const float* src = use_r1 ? d_rnn1 : xin;
    int dir = blockIdx.y;
    int s0  = blockIdx.x * 2;
    int t   = threadIdx.x;
    for (int n = t; n < SB * 2 * K; n += 512) {
        int b = n / (2 * K); int rem = n % (2 * K);
        int sl = rem / K;    int k = rem % K;
        xsh[b][sl][k] = src[(b * SEQ + s0 + sl) * K + k];
    }
    __syncthreads();
    const float* w = (dir ? wB : wF) + t * K;
    float bias = (dir ? bB : bF)[t];
    float a00 = bias, a01 = bias, a10 = bias, a11 = bias;
    const float4* w4 = (const float4*)w;
    int K4 = K >> 2;
    for (int k4 = 0; k4 < K4; k4++) {
        float4 wv = w4[k4]; int k = k4 * 4;
        a00 += wv.x*xsh[0][0][k] + wv.y*xsh[0][0][k+1] + wv.z*xsh[0][0][k+2] + wv.w*xsh[0][0][k+3];
        a01 += wv.x*xsh[0][1][k] + wv.y*xsh[0][1][k+1] + wv.z*xsh[0][1][k+2] + wv.w*xsh[0][1][k+3];
        a10 += wv.x*xsh[1][0][k] + wv.y*xsh[1][0][k+1] + wv.z*xsh[1][0][k+2] + wv.w*xsh[1][0][k+3];
        a11 += wv.x*xsh[1][1][k] + wv.y*xsh[1][1][k+1] + wv.z*xsh[1][1][k+2] + wv.w*xsh[1][1][k+3];
    }
    d_pre[((dir*SEQ + s0    ) * SB + 0) * G4 + t] = a00;
    d_pre[((dir*SEQ + s0    ) * SB + 1) * G4 + t] = a10;
    d_pre[((dir*SEQ + s0 + 1) * SB + 0) * G4 + t] = a01;
    d_pre[((dir*SEQ + s0 + 1) * SB + 1) * G4 + t] = a11;
}

// ---------------- LSTM recurrence: one 4-CTA cluster per direction ----------------
// grid 8 = 2 clusters of 4. CTA cr owns h indices j in [32cr, 32cr+32) (x4 gates).
// Thread t: rl=t>>1 row-local, half=t&1 owns 64 of the 128 k's (weights in regs).
// Per-step sync: writer warps (0,1) DSMEM-broadcast h, then one elected lane per
// writer warp arrives on every cluster CTA's mbarrier (count=8). No cluster.sync
// in the loop -> no CCTL.IVALL L1 flush, wait is a cheap TRYWAIT.
__global__ __launch_bounds__(256, 1) __cluster_dims__(4, 1, 1)
void lstm_kernel(const float* __restrict__ whhF, const float* __restrict__ whhB,
                 int out_is_l2)
{
    cg::cluster_group cluster = cg::this_cluster();
    float* out = out_is_l2 ? d_rnn2 : d_rnn1;
    int blk = blockIdx.x, dir = blk >> 2, cr = blk & 3;
    const float* whh = dir ? whhB : whhF;
    int t = threadIdx.x;
    int rl = t >> 1, half = t & 1, gate = rl >> 5, jj = rl & 31;
    int g = gate * HID + cr * 32 + jj;

    float w[64];
    const float4* wr = (const float4*)(whh + g * HID + half * 64);
#pragma unroll
    for (int q = 0; q < 16; q++) {
        float4 v = wr[q];
        w[4*q] = v.x; w[4*q+1] = v.y; w[4*q+2] = v.z; w[4*q+3] = v.w;
    }

    __shared__ float hsm[2][SB * HID];     // double-buffered h, full 256 vector
    __shared__ float gsm[SB][4][32];
    __shared__ __align__(8) unsigned long long mbar;
    uint32_t bar = smem_u32(&mbar);
    float c = 0.f;
    int cb = t >> 5, cjl = t & 31;         // cell mapping for t<64
    int cj = cr * 32 + cjl;

    hsm[0][t] = 0.f;                       // ts=0 reads buffer 0
    if (t == 0) mbar_init(bar, 8);         // 2 writer warps x 4 CTAs

    // peer smem base pointers (same layout in every CTA of the cluster)
    float* peer[4];
#pragma unroll
    for (int r = 0; r < 4; r++) peer[r] = cluster.map_shared_rank(&hsm[0][0], r);

    cluster.sync();                        // init + mbarriers visible; peers resident

    for (int ts = 0; ts < SEQ; ts++) {
        int s = dir ? (SEQ - 1 - ts) : ts;
        int rb = ts & 1, wb = rb ^ 1;
        float pre0 = d_pre[((dir*SEQ + s) * SB + 0) * G4 + g];
        float pre1 = d_pre[((dir*SEQ + s) * SB + 1) * G4 + g];

        const float4* h0 = (const float4*)&hsm[rb][0 * HID + half * 64];
        const float4* h1 = (const float4*)&hsm[rb][1 * HID + half * 64];
        float a0 = 0.f, a1 = 0.f;
#pragma unroll
        for (int q = 0; q < 16; q++) {
            float4 v0 = h0[q], v1 = h1[q];
            a0 += w[4*q]*v0.x + w[4*q+1]*v0.y + w[4*q+2]*v0.z + w[4*q+3]*v0.w;
            a1 += w[4*q]*v1.x + w[4*q+1]*v1.y + w[4*q+2]*v1.z + w[4*q+3]*v1.w;
        }
        a0 += __shfl_xor_sync(0xffffffffu, a0, 1);
        a1 += __shfl_xor_sync(0xffffffffu, a1, 1);
        if (half == 0) {
            gsm[0][gate][jj] = pre0 + a0;
            gsm[1][gate][jj] = pre1 + a1;
        }
        // after this barrier: every local warp is done reading hsm[rb] and gsm
        __syncthreads();
        if (t < 64) {
            float gi = gsm[cb][0][cjl], gf = gsm[cb][1][cjl];
            float gg = gsm[cb][2][cjl], go = gsm[cb][3][cjl];
            c = sigmf(gf) * c + sigmf(gi) * tanhf(gg);
            float h = sigmf(go) * tanhf(c);
            int off = wb * (SB * HID) + cb * HID + cj;
#pragma unroll
            for (int r = 0; r < 4; r++) peer[r][off] = h;   // DSMEM broadcast
            out[(cb * SEQ + s) * F2D + dir * HID + cj] = h;
            __syncwarp();                                   // order stores before elected arrive
            if (cjl == 0) {                                 // lane 0 of warps 0,1
#pragma unroll
                for (int r = 0; r < 4; r++) mbar_arrive_rank(bar, (uint32_t)r);
            }
        }
        mbar_wait_cluster(bar, (uint32_t)(ts & 1));
    }
}

// ---------------- inclusive cumsum over s ----------------
__global__ void cumsum_kernel() {
    int b = blockIdx.x, k = threadIdx.x;
    float acc = 0.f;
#pragma unroll 8
    for (int s = 0; s < SEQ; s++) {
        acc += d_rnn2[(b * SEQ + s) * F2D + k];
        d_cum[(b * SEQ + s) * F2D + k] = acc;
    }
}

// ---------------- per-position d/e parts of score MLP layer 1 ----------------
__global__ __launch_bounds__(128) void pdpe_kernel(
    const float* __restrict__ w1, const float* __restrict__ b1,
    const float* __restrict__ a0p)
{
    int b = blockIdx.x >> 8, s = blockIdx.x & 255, t = threadIdx.x;
    float a0 = *a0p;
    __shared__ float px[F2D];
    for (int k = t; k < F2D; k += 128) px[k] = preluf(d_rnn2[(b * SEQ + s) * F2D + k], a0);
    __syncthreads();
    if (t < HS) {
        const float4* wd = (const float4*)(w1 + t * 768 + 256);
        const float4* we = (const float4*)(w1 + t * 768 + 512);
        float ad = 0.f, ae = 0.f;
        for (int k4 = 0; k4 < 64; k4++) {
            float4 v = wd[k4], u = we[k4]; int k = k4 * 4;
            ad += v.x*px[k] + v.y*px[k+1] + v.z*px[k+2] + v.w*px[k+3];
            ae += u.x*px[k] + u.y*px[k+1] + u.z*px[k+2] + u.w*px[k+3];
        }
        d_pd[(b * SEQ + s) * HS + t] = ad;
        d_pe[(b * SEQ + s) * HS + t] = ae + b1[t];
    }
}

// ---------------- cls + bin MLPs ----------------
__global__ __launch_bounds__(160) void clsbin_kernel(
    const float* a_c0, const float* w_c1, const float* b_c1,
    const float* a_c1, const float* w_c2, const float* b_c2,
    const float* a_b0, const float* w_b1, const float* b_b1,
    const float* a_b1, const float* w_b2, const float* b_b2,
    float* __restrict__ out)
{
    int b = blockIdx.x >> 8, s = blockIdx.x & 255, t = threadIdx.x;
    __shared__ float xr[F2D];
    __shared__ float hc[80], hb[80];
    for (int k = t; k < F2D; k += 160) xr[k] = d_rnn2[(b * SEQ + s) * F2D + k];
    __syncthreads();
    {
        int row = t % 80;
        bool isb = t >= 80;
        const float4* wrow = (const float4*)((isb ? w_b1 : w_c1) + row * F2D);
        float alpha = isb ? *a_b0 : *a_c0;
        float acc = (isb ? b_b1 : b_c1)[row];
        for (int k4 = 0; k4 < 64; k4++) {
            float4 wv = wrow[k4]; int k = k4 * 4;
            acc += wv.x * preluf(xr[k],   alpha) + wv.y * preluf(xr[k+1], alpha)
                 + wv.z * preluf(xr[k+2], alpha) + wv.w * preluf(xr[k+3], alpha);
        }
        if (isb) hb[row] = acc; else hc[row] = acc;
    }
    __syncthreads();
    if (t < NCLS) {
        float a1 = *a_c1, acc = b_c2[t];
        for (int q = 0; q < 80; q++) acc += w_c2[t * 80 + q] * preluf(hc[q], a1);
        out[(b * SEQ + s) * NCLS + t] = acc;
    } else if (t < NCLS + 2) {
        int r = t - NCLS;
        float a1 = *a_b1, acc = b_b2[r];
        for (int q = 0; q < 80; q++) acc += w_b2[r * 80 + q] * preluf(hb[q], a1);
        out[SB*SEQ*NCLS + (b * SEQ + s) * 2 + r] = acc;
    }
}

// ---------------- banded pairwise scores ----------------
// grid 510: b = bid&1, i = 1 + (bid>>1). smem: phi(64 x 256 padded) + W1c(112 x 256 padded)
#define RPAD 65   // float4 row stride (260 floats) -> 2-way bank conflicts only
__global__ __launch_bounds__(256) void band_kernel(
    const float* __restrict__ w1, const float* __restrict__ w2,
    const float* __restrict__ b2, const float* __restrict__ a0p,
    const float* __restrict__ a1p)
{
    extern __shared__ float smraw[];
    float4* phi = (float4*)smraw;
    float4* w1s = phi + 64 * RPAD;
    int b = blockIdx.x & 1;
    int i = 1 + (blockIdx.x >> 1);
    int start = i > WSEG ? i - WSEG : 0;
    int t = threadIdx.x;
    float a0 = *a0p;

    for (int n = t; n < 112 * 64; n += 256) {           // stage W1 cols [0,256)
        int r = n >> 6, k4 = n & 63;
        float4 v = make_float4(0.f, 0.f, 0.f, 0.f);
        if (r < HS) v = ((const float4*)(w1 + r * 768))[k4];
        w1s[r * RPAD + k4] = v;
    }
    const float4* cum4 = (const float4*)d_cum;
    for (int n = t; n < 64 * 64; n += 256) {            // phi = prelu(cum_i - cum_j)
        int wdx = n >> 6, k4 = n & 63;
        int j = start + wdx;
        float4 ci = cum4[(b * SEQ + i) * 64 + k4];
        float4 cj = cum4[(b * SEQ + j) * 64 + k4];
        float4 d;
        d.x = preluf(ci.x - cj.x, a0); d.y = preluf(ci.y - cj.y, a0);
        d.z = preluf(ci.z - cj.z, a0); d.w = preluf(ci.w - cj.w, a0);
        phi[wdx * RPAD + k4] = d;
    }
    __syncthreads();

    int tw = t & 15, tr = t >> 4;
    float acc[4][7];
#pragma unroll
    for (int q = 0; q < 4; q++)
#pragma unroll
        for (int p = 0; p < 7; p++) acc[q][p] = 0.f;

    for (int k4 = 0; k4 < 64; k4++) {
        float4 ph[4];
#pragma unroll
        for (int q = 0; q < 4; q++) ph[q] = phi[(tr + 16 * q) * RPAD + k4];
#pragma unroll
        for (int p = 0; p < 7; p++) {
            float4 wv = w1s[(tw + 16 * p) * RPAD + k4];
#pragma unroll
            for (int q = 0; q < 4; q++)
                acc[q][p] += ph[q].x*wv.x + ph[q].y*wv.y + ph[q].z*wv.z + ph[q].w*wv.w;
        }
    }

    float a1 = *a1p;
    float loc[4] = {0.f, 0.f, 0.f, 0.f};
#pragma unroll
    for (int p = 0; p < 7; p++) {
        int r = tw + 16 * p;
        float w2v = (r < HS) ? w2[r] : 0.f;
        float pev = (r < HS) ? d_pe[(b * SEQ + i) * HS + r] : 0.f;
#pragma unroll
        for (int q = 0; q < 4; q++) {
            int j = start + tr + 16 * q;
            float pdv = (r < HS) ? d_pd[(b * SEQ + j) * HS + r] : 0.f;
            float h = acc[q][p] + pdv + pev;
            loc[q] += preluf(h, a1) * w2v;
        }
    }
#pragma unroll
    for (int off = 8; off >= 1; off >>= 1)
#pragma unroll
        for (int q = 0; q < 4; q++)
            loc[q] += __shfl_xor_sync(0xffffffffu, loc[q], off, 16);
    if (tw == 0) {
        float bb = b2[0];
#pragma unroll
        for (int q = 0; q < 4; q++)
            d_band[(b * SEQ + i) * WSEG + tr + 16 * q] = loc[q] + bb;
    }
}

// ---------------- DP + backtrack (single CTA, band in smem) ----------------
__global__ __launch_bounds__(256) void dp_kernel(const int* __restrict__ lengths,
                                                 float* __restrict__ out)
{
    extern __shared__ float bs[];               // 2*256*64 floats
    __shared__ float best[SB][SEQ];
    __shared__ int   bp[SB][SEQ];
    int t = threadIdx.x;
    const float4* src = (const float4*)d_band;
    float4* dst = (float4*)bs;
    for (int n = t; n < SB * SEQ * WSEG / 4; n += 256) dst[n] = src[n];
    float* bm = out + SB*SEQ*NCLS + SB*SEQ*2;
    for (int n = t; n < SB * SEQ; n += 256) bm[n] = 0.f;
    if (t < SB) { best[t][0] = 0.f; bp[t][0] = 0; }
    __syncthreads();

    if (t < 64) {
        int b = t >> 5, l = t & 31;
        for (int i = 1; i < SEQ; i++) {
            int start = i > WSEG ? i - WSEG : 0;
            const float* row = &bs[(b * SEQ + i) * WSEG];
            int j1 = start + l;
            float v1 = (j1 < i) ? best[b][j1] + row[l] : -1e9f;
            int j2 = start + l + 32;
            float v2 = (j2 < i) ? best[b][j2] + row[l + 32] : -1e9f;
            float v; int wj;
            if (v2 > v1) { v = v2; wj = j2; } else { v = v1; wj = j1; }
#pragma unroll
            for (int off = 16; off >= 1; off >>= 1) {
                float ov = __shfl_xor_sync(0xffffffffu, v, off);
                int   oj = __shfl_xor_sync(0xffffffffu, wj, off);
                if (ov > v || (ov == v && oj < wj)) { v = ov; wj = oj; }
            }
            if (l == 0) { best[b][i] = v; bp[b][i] = wj; }
            __syncwarp();
        }
    }
    __syncthreads();
    if (t == 0 || t == 32) {
        int b = t >> 5;
        int cur = lengths[b] - 1;
        float acc = 0.f;
        while (true) {
            bm[b * SEQ + cur] = 1.f;
            if (cur == 0) break;
            int prev = bp[b][cur];
            int start = cur > WSEG ? cur - WSEG : 0;
            acc += bs[(b * SEQ + cur) * WSEG + (prev - start)];
            cur = prev;
        }
        out[SB*SEQ*NCLS + SB*SEQ*2 + SB*SEQ + b] = acc;
    }
}

// ---------------- launch ----------------
extern "C" void kernel_launch(void* const* d_in, const int* in_sizes, int n_in,
                              void* d_out, int out_size)
{
    const float* x      = (const float*)d_in[0];
    const int*   lens   = (const int*)  d_in[1];
    const float* wih0f  = (const float*)d_in[2];
    const float* whh0f  = (const float*)d_in[3];
    const float* b0f    = (const float*)d_in[4];
    const float* wih0b  = (const float*)d_in[5];
    const float* whh0b  = (const float*)d_in[6];
    const float* b0b    = (const float*)d_in[7];
    const float* wih1f  = (const float*)d_in[8];
    const float* whh1f  = (const float*)d_in[9];
    const float* b1f    = (const float*)d_in[10];
    const float* wih1b  = (const float*)d_in[11];
    const float* whh1b  = (const float*)d_in[12];
    const float* b1b    = (const float*)d_in[13];
    const float* a_s0   = (const float*)d_in[14];
    const float* w_s1   = (const float*)d_in[15];
    const float* b_s1   = (const float*)d_in[16];
    const float* a_s1   = (const float*)d_in[17];
    const float* w_s2   = (const float*)d_in[18];
    const float* b_s2   = (const float*)d_in[19];
    const float* a_c0   = (const float*)d_in[20];
    const float* w_c1   = (const float*)d_in[21];
    const float* b_c1   = (const float*)d_in[22];
    const float* a_c1   = (const float*)d_in[23];
    const float* w_c2   = (const float*)d_in[24];
    const float* b_c2   = (const float*)d_in[25];
    const float* a_b0   = (const float*)d_in[26];
    const float* w_b1   = (const float*)d_in[27];
    const float* b_b1   = (const float*)d_in[28];
    const float* a_b1   = (const float*)d_in[29];
    const float* w_b2   = (const float*)d_in[30];
    const float* b_b2   = (const float*)d_in[31];
    float* out = (float*)d_out;

    cudaFuncSetAttribute(band_kernel, cudaFuncAttributeMaxDynamicSharedMemorySize, 183040);
    cudaFuncSetAttribute(dp_kernel,   cudaFuncAttributeMaxDynamicSharedMemorySize, 131072);

    proj_kernel<<<dim3(128, 2), 512>>>(x, IND, 0, wih0f, b0f, wih0b, b0b);
    lstm_kernel<<<8, 256>>>(whh0f, whh0b, 0);
    proj_kernel<<<dim3(128, 2), 512>>>(x, F2D, 1, wih1f, b1f, wih1b, b1b);
    lstm_kernel<<<8, 256>>>(whh1f, whh1b, 1);
    cumsum_kernel<<<2, 256>>>();
    pdpe_kernel<<<512, 128>>>(w_s1, b_s1, a_s0);
    clsbin_kernel<<<512, 160>>>(a_c0, w_c1, b_c1, a_c1, w_c2, b_c2,
                                a_b0, w_b1, b_b1, a_b1, w_b2, b_b2, out);
    band_kernel<<<510, 256, 183040>>>(w_s1, w_s2, b_s2, a_s0, a_s1);
    dp_kernel<<<1, 256, 131072>>>(lens, out);
}

// round 14
// speedup vs baseline: 1.9466x; 1.0785x over previous
#include <cuda_runtime.h>
#include <cooperative_groups.h>
#include <math.h>

namespace cg = cooperative_groups;

#define SB   2
#define SEQ  256
#define IND  80
#define HID  128
#define G4   512
#define F2D  256
#define NCLS 40
#define WSEG 64
#define HS   100

// ---------------- device scratch ----------------
__device__ float    d_pre [2*SEQ*SB*G4];   // [dir][s][b][512]
__device__ float    d_rnn1[SB*SEQ*F2D];
__device__ float    d_rnn2[SB*SEQ*F2D];
__device__ float    d_cum [SB*SEQ*F2D];
__device__ float    d_pd  [SB*SEQ*HS];
__device__ float    d_pe  [SB*SEQ*HS];
__device__ float    d_band[SB*SEQ*WSEG];   // band[b][i][w], j = max(0,i-64)+w

__device__ __forceinline__ float preluf(float x, float a) { return x >= 0.f ? x : a * x; }
// fast, NaN-safe gate activations (__expf: MUFU-based, ~1e-6 rel err)
__device__ __forceinline__ float fsigm(float x) { return 1.f / (1.f + __expf(-x)); }
__device__ __forceinline__ float ftanh(float x) {
    float e = __expf(-2.f * fabsf(x));
    float t = (1.f - e) / (1.f + e);
    return copysignf(t, x);
}

__device__ __forceinline__ uint32_t smem_u32(const void* p) {
    uint32_t a;
    asm("{ .reg .u64 t; cvta.to.shared.u64 t, %1; cvt.u32.u64 %0, t; }" : "=r"(a) : "l"(p));
    return a;
}
__device__ __forceinline__ void mbar_init(uint32_t bar, uint32_t cnt) {
    asm volatile("mbarrier.init.shared.b64 [%0], %1;" :: "r"(bar), "r"(cnt) : "memory");
}
// arrive on the mbarrier at the same smem offset in cluster CTA `rank` (release.cluster)
__device__ __forceinline__ void mbar_arrive_rank(uint32_t bar, uint32_t rank) {
    asm volatile(
        "{\n\t.reg .b32 r;\n\t"
        "mapa.shared::cluster.u32 r, %0, %1;\n\t"
        "mbarrier.arrive.shared::cluster.b64 _, [r];\n\t}"
        :: "r"(bar), "r"(rank) : "memory");
}
// wait for phase `parity` completion with cluster-scope acquire
__device__ __forceinline__ void mbar_wait_cluster(uint32_t bar, uint32_t parity) {
    asm volatile(
        "{\n\t.reg .pred P;\n\t"
        "LW%=:\n\t"
        "mbarrier.try_wait.parity.acquire.cluster.shared::cta.b64 P, [%0], %1, 0x989680;\n\t"
        "@P bra LD%=;\n\t"
        "bra LW%=;\n\t"
        "LD%=:\n\t}"
        :: "r"(bar), "r"(parity) : "memory");
}

// ---------------- input projection: pre = x @ Wih^T + b ----------------
// grid (S/2, 2 dirs), block 512 (one thread per gate row)
__global__ __launch_bounds__(512) void proj_kernel(
    const float* __restrict__ xin, int K, int use_r1,
    const float* __restrict__ wF, const float* __restrict__ bF,
    const float* __restrict__ wB, const float* __restrict__ bB)
{
    __shared__ float xsh[SB][2][F2D];
    const float* src = use_r1 ? d_rnn1 : xin;
    int dir = blockIdx.y;
    int s0  = blockIdx.x * 2;
    int t   = threadIdx.x;
    for (int n = t; n < SB * 2 * K; n += 512) {
        int b = n / (2 * K); int rem = n % (2 * K);
        int sl = rem / K;    int k = rem % K;
        xsh[b][sl][k] = src[(b * SEQ + s0 + sl) * K + k];
    }
    __syncthreads();
    const float* w = (dir ? wB : wF) + t * K;
    float bias = (dir ? bB : bF)[t];
    float a00 = bias, a01 = bias, a10 = bias, a11 = bias;
    const float4* w4 = (const float4*)w;
    int K4 = K >> 2;
    for (int k4 = 0; k4 < K4; k4++) {
        float4 wv = w4[k4]; int k = k4 * 4;
        a00 += wv.x*xsh[0][0][k] + wv.y*xsh[0][0][k+1] + wv.z*xsh[0][0][k+2] + wv.w*xsh[0][0][k+3];
        a01 += wv.x*xsh[0][1][k] + wv.y*xsh[0][1][k+1] + wv.z*xsh[0][1][k+2] + wv.w*xsh[0][1][k+3];
        a10 += wv.x*xsh[1][0][k] + wv.y*xsh[1][0][k+1] + wv.z*xsh[1][0][k+2] + wv.w*xsh[1][0][k+3];
        a11 += wv.x*xsh[1][1][k] + wv.y*xsh[1][1][k+1] + wv.z*xsh[1][1][k+2] + wv.w*xsh[1][1][k+3];
    }
    d_pre[((dir*SEQ + s0    ) * SB + 0) * G4 + t] = a00;
    d_pre[((dir*SEQ + s0    ) * SB + 1) * G4 + t] = a10;
    d_pre[((dir*SEQ + s0 + 1) * SB + 0) * G4 + t] = a01;
    d_pre[((dir*SEQ + s0 + 1) * SB + 1) * G4 + t] = a11;
}

// ---------------- LSTM recurrence: one 4-CTA cluster per (direction, batch) ----------------
// grid 16 = 4 clusters of 4. Cluster cid: dir=cid>>1, batch=cid&1.
// CTA cr owns h indices j in [32cr, 32cr+32) (x4 gates -> 128 gate rows).
// Thread t: rl=t>>1 row-local, half=t&1 owns 64 of the 128 k's (weights in regs).
// Per-step sync: writer warp (t<32) DSMEM-broadcasts h; lane 0 arrives on all 4
// CTAs' mbarriers (count=4). No cluster.sync in loop -> no L1 flush.
__global__ __launch_bounds__(256, 1) __cluster_dims__(4, 1, 1)
void lstm_kernel(const float* __restrict__ whhF, const float* __restrict__ whhB,
                 int out_is_l2)
{
    cg::cluster_group cluster = cg::this_cluster();
    float* out = out_is_l2 ? d_rnn2 : d_rnn1;
    int blk = blockIdx.x;
    int cid = blk >> 2;
    int dir = cid >> 1, bat = cid & 1, cr = blk & 3;
    const float* whh = dir ? whhB : whhF;
    int t = threadIdx.x;
    int rl = t >> 1, half = t & 1, gate = rl >> 5, jj = rl & 31;
    int g = gate * HID + cr * 32 + jj;

    float w[64];
    const float4* wr = (const float4*)(whh + g * HID + half * 64);
#pragma unroll
    for (int q = 0; q < 16; q++) {
        float4 v = wr[q];
        w[4*q] = v.x; w[4*q+1] = v.y; w[4*q+2] = v.z; w[4*q+3] = v.w;
    }

    __shared__ float hsm[2][HID];          // double-buffered h (single batch)
    __shared__ float gsm[4][32];
    __shared__ __align__(8) unsigned long long mbar;
    uint32_t bar = smem_u32(&mbar);
    float c = 0.f;

    if (t < HID) hsm[0][t] = 0.f;          // ts=0 reads buffer 0
    if (t == 0) mbar_init(bar, 4);         // 1 elected lane x 4 CTAs

    float* peer[4];
#pragma unroll
    for (int r = 0; r < 4; r++) peer[r] = cluster.map_shared_rank(&hsm[0][0], r);

    cluster.sync();                        // init + mbarriers visible; peers resident

    const float* preb = d_pre + (dir * SEQ) * (SB * G4) + bat * G4 + g;

    for (int ts = 0; ts < SEQ; ts++) {
        int s = dir ? (SEQ - 1 - ts) : ts;
        int rb = ts & 1, wb = rb ^ 1;
        float pre = preb[s * (SB * G4)];

        const float4* h0 = (const float4*)&hsm[rb][half * 64];
        float a = 0.f;
#pragma unroll
        for (int q = 0; q < 16; q++) {
            float4 v0 = h0[q];
            a += w[4*q]*v0.x + w[4*q+1]*v0.y + w[4*q+2]*v0.z + w[4*q+3]*v0.w;
        }
        a += __shfl_xor_sync(0xffffffffu, a, 1);
        if (half == 0) gsm[gate][jj] = pre + a;
        // after this barrier: every local warp done reading hsm[rb] and gsm
        __syncthreads();
        if (t < 32) {
            float gi = gsm[0][t], gf = gsm[1][t];
            float gg = gsm[2][t], go = gsm[3][t];
            c = fsigm(gf) * c + fsigm(gi) * ftanh(gg);
            float h = fsigm(go) * ftanh(c);
            int cj = cr * 32 + t;
            int off = wb * HID + cj;
#pragma unroll
            for (int r = 0; r < 4; r++) peer[r][off] = h;   // DSMEM broadcast
            out[(bat * SEQ + s) * F2D + dir * HID + cj] = h;
            __syncwarp();                                   // stores before elected arrive
            if (t == 0) {
#pragma unroll
                for (int r = 0; r < 4; r++) mbar_arrive_rank(bar, (uint32_t)r);
            }
        }
        mbar_wait_cluster(bar, (uint32_t)(ts & 1));
    }
}

// ---------------- inclusive cumsum over s ----------------
__global__ void cumsum_kernel() {
    int b = blockIdx.x, k = threadIdx.x;
    float acc = 0.f;
#pragma unroll 8
    for (int s = 0; s < SEQ; s++) {
        acc += d_rnn2[(b * SEQ + s) * F2D + k];
        d_cum[(b * SEQ + s) * F2D + k] = acc;
    }
}

// ---------------- per-position d/e parts of score MLP layer 1 ----------------
__global__ __launch_bounds__(128) void pdpe_kernel(
    const float* __restrict__ w1, const float* __restrict__ b1,
    const float* __restrict__ a0p)
{
    int b = blockIdx.x >> 8, s = blockIdx.x & 255, t = threadIdx.x;
    float a0 = *a0p;
    __shared__ float px[F2D];
    for (int k = t; k < F2D; k += 128) px[k] = preluf(d_rnn2[(b * SEQ + s) * F2D + k], a0);
    __syncthreads();
    if (t < HS) {
        const float4* wd = (const float4*)(w1 + t * 768 + 256);
        const float4* we = (const float4*)(w1 + t * 768 + 512);
        float ad = 0.f, ae = 0.f;
        for (int k4 = 0; k4 < 64; k4++) {
            float4 v = wd[k4], u = we[k4]; int k = k4 * 4;
            ad += v.x*px[k] + v.y*px[k+1] + v.z*px[k+2] + v.w*px[k+3];
            ae += u.x*px[k] + u.y*px[k+1] + u.z*px[k+2] + u.w*px[k+3];
        }
        d_pd[(b * SEQ + s) * HS + t] = ad;
        d_pe[(b * SEQ + s) * HS + t] = ae + b1[t];
    }
}

// ---------------- cls + bin MLPs ----------------
__global__ __launch_bounds__(160) void clsbin_kernel(
    const float* a_c0, const float* w_c1, const float* b_c1,
    const float* a_c1, const float* w_c2, const float* b_c2,
    const float* a_b0, const float* w_b1, const float* b_b1,
    const float* a_b1, const float* w_b2, const float* b_b2,
    float* __restrict__ out)
{
    int b = blockIdx.x >> 8, s = blockIdx.x & 255, t = threadIdx.x;
    __shared__ float xr[F2D];
    __shared__ float hc[80], hb[80];
    for (int k = t; k < F2D; k += 160) xr[k] = d_rnn2[(b * SEQ + s) * F2D + k];
    __syncthreads();
    {
        int row = t % 80;
        bool isb = t >= 80;
        const float4* wrow = (const float4*)((isb ? w_b1 : w_c1) + row * F2D);
        float alpha = isb ? *a_b0 : *a_c0;
        float acc = (isb ? b_b1 : b_c1)[row];
        for (int k4 = 0; k4 < 64; k4++) {
            float4 wv = wrow[k4]; int k = k4 * 4;
            acc += wv.x * preluf(xr[k],   alpha) + wv.y * preluf(xr[k+1], alpha)
                 + wv.z * preluf(xr[k+2], alpha) + wv.w * preluf(xr[k+3], alpha);
        }
        if (isb) hb[row] = acc; else hc[row] = acc;
    }
    __syncthreads();
    if (t < NCLS) {
        float a1 = *a_c1, acc = b_c2[t];
        for (int q = 0; q < 80; q++) acc += w_c2[t * 80 + q] * preluf(hc[q], a1);
        out[(b * SEQ + s) * NCLS + t] = acc;
    } else if (t < NCLS + 2) {
        int r = t - NCLS;
        float a1 = *a_b1, acc = b_b2[r];
        for (int q = 0; q < 80; q++) acc += w_b2[r * 80 + q] * preluf(hb[q], a1);
        out[SB*SEQ*NCLS + (b * SEQ + s) * 2 + r] = acc;
    }
}

// ---------------- banded pairwise scores ----------------
// grid 510: b = bid&1, i = 1 + (bid>>1). smem: phi(64 x 256 padded) + W1c(112 x 256 padded)
#define RPAD 65   // float4 row stride (260 floats) -> 2-way bank conflicts only
__global__ __launch_bounds__(256) void band_kernel(
    const float* __restrict__ w1, const float* __restrict__ w2,
    const float* __restrict__ b2, const float* __restrict__ a0p,
    const float* __restrict__ a1p)
{
    extern __shared__ float smraw[];
    float4* phi = (float4*)smraw;
    float4* w1s = phi + 64 * RPAD;
    int b = blockIdx.x & 1;
    int i = 1 + (blockIdx.x >> 1);
    int start = i > WSEG ? i - WSEG : 0;
    int t = threadIdx.x;
    float a0 = *a0p;

    for (int n = t; n < 112 * 64; n += 256) {           // stage W1 cols [0,256)
        int r = n >> 6, k4 = n & 63;
        float4 v = make_float4(0.f, 0.f, 0.f, 0.f);
        if (r < HS) v = ((const float4*)(w1 + r * 768))[k4];
        w1s[r * RPAD + k4] = v;
    }
    const float4* cum4 = (const float4*)d_cum;
    for (int n = t; n < 64 * 64; n += 256) {            // phi = prelu(cum_i - cum_j)
        int wdx = n >> 6, k4 = n & 63;
        int j = start + wdx;
        float4 ci = cum4[(b * SEQ + i) * 64 + k4];
        float4 cj = cum4[(b * SEQ + j) * 64 + k4];
        float4 d;
        d.x = preluf(ci.x - cj.x, a0); d.y = preluf(ci.y - cj.y, a0);
        d.z = preluf(ci.z - cj.z, a0); d.w = preluf(ci.w - cj.w, a0);
        phi[wdx * RPAD + k4] = d;
    }
    __syncthreads();

    int tw = t & 15, tr = t >> 4;
    float acc[4][7];
#pragma unroll
    for (int q = 0; q < 4; q++)
#pragma unroll
        for (int p = 0; p < 7; p++) acc[q][p] = 0.f;

    for (int k4 = 0; k4 < 64; k4++) {
        float4 ph[4];
#pragma unroll
        for (int q = 0; q < 4; q++) ph[q] = phi[(tr + 16 * q) * RPAD + k4];
#pragma unroll
        for (int p = 0; p < 7; p++) {
            float4 wv = w1s[(tw + 16 * p) * RPAD + k4];
#pragma unroll
            for (int q = 0; q < 4; q++)
                acc[q][p] += ph[q].x*wv.x + ph[q].y*wv.y + ph[q].z*wv.z + ph[q].w*wv.w;
        }
    }

    float a1 = *a1p;
    float loc[4] = {0.f, 0.f, 0.f, 0.f};
#pragma unroll
    for (int p = 0; p < 7; p++) {
        int r = tw + 16 * p;
        float w2v = (r < HS) ? w2[r] : 0.f;
        float pev = (r < HS) ? d_pe[(b * SEQ + i) * HS + r] : 0.f;
#pragma unroll
        for (int q = 0; q < 4; q++) {
            int j = start + tr + 16 * q;
            float pdv = (r < HS) ? d_pd[(b * SEQ + j) * HS + r] : 0.f;
            float h = acc[q][p] + pdv + pev;
            loc[q] += preluf(h, a1) * w2v;
        }
    }
#pragma unroll
    for (int off = 8; off >= 1; off >>= 1)
#pragma unroll
        for (int q = 0; q < 4; q++)
            loc[q] += __shfl_xor_sync(0xffffffffu, loc[q], off, 16);
    if (tw == 0) {
        float bb = b2[0];
#pragma unroll
        for (int q = 0; q < 4; q++)
            d_band[(b * SEQ + i) * WSEG + tr + 16 * q] = loc[q] + bb;
    }
}

// ---------------- DP + backtrack (single CTA, band in smem) ----------------
__global__ __launch_bounds__(256) void dp_kernel(const int* __restrict__ lengths,
                                                 float* __restrict__ out)
{
    extern __shared__ float bs[];               // 2*256*64 floats
    __shared__ float best[SB][SEQ];
    __shared__ int   bp[SB][SEQ];
    int t = threadIdx.x;
    const float4* src = (const float4*)d_band;
    float4* dst = (float4*)bs;
    for (int n = t; n < SB * SEQ * WSEG / 4; n += 256) dst[n] = src[n];
    float* bm = out + SB*SEQ*NCLS + SB*SEQ*2;
    for (int n = t; n < SB * SEQ; n += 256) bm[n] = 0.f;
    if (t < SB) { best[t][0] = 0.f; bp[t][0] = 0; }
    __syncthreads();

    if (t < 64) {
        int b = t >> 5, l = t & 31;
        for (int i = 1; i < SEQ; i++) {
            int start = i > WSEG ? i - WSEG : 0;
            const float* row = &bs[(b * SEQ + i) * WSEG];
            int j1 = start + l;
            float v1 = (j1 < i) ? best[b][j1] + row[l] : -1e9f;
            int j2 = start + l + 32;
            float v2 = (j2 < i) ? best[b][j2] + row[l + 32] : -1e9f;
            float v; int wj;
            if (v2 > v1) { v = v2; wj = j2; } else { v = v1; wj = j1; }
#pragma unroll
            for (int off = 16; off >= 1; off >>= 1) {
                float ov = __shfl_xor_sync(0xffffffffu, v, off);
                int   oj = __shfl_xor_sync(0xffffffffu, wj, off);
                if (ov > v || (ov == v && oj < wj)) { v = ov; wj = oj; }
            }
            if (l == 0) { best[b][i] = v; bp[b][i] = wj; }
            __syncwarp();
        }
    }
    __syncthreads();
    if (t == 0 || t == 32) {
        int b = t >> 5;
        int cur = lengths[b] - 1;
        float acc = 0.f;
        while (true) {
            bm[b * SEQ + cur] = 1.f;
            if (cur == 0) break;
            int prev = bp[b][cur];
            int start = cur > WSEG ? cur - WSEG : 0;
            acc += bs[(b * SEQ + cur) * WSEG + (prev - start)];
            cur = prev;
        }
        out[SB*SEQ*NCLS + SB*SEQ*2 + SB*SEQ + b] = acc;
    }
}

// ---------------- launch ----------------
extern "C" void kernel_launch(void* const* d_in, const int* in_sizes, int n_in,
                              void* d_out, int out_size)
{
    const float* x      = (const float*)d_in[0];
    const int*   lens   = (const int*)  d_in[1];
    const float* wih0f  = (const float*)d_in[2];
    const float* whh0f  = (const float*)d_in[3];
    const float* b0f    = (const float*)d_in[4];
    const float* wih0b  = (const float*)d_in[5];
    const float* whh0b  = (const float*)d_in[6];
    const float* b0b    = (const float*)d_in[7];
    const float* wih1f  = (const float*)d_in[8];
    const float* whh1f  = (const float*)d_in[9];
    const float* b1f    = (const float*)d_in[10];
    const float* wih1b  = (const float*)d_in[11];
    const float* whh1b  = (const float*)d_in[12];
    const float* b1b    = (const float*)d_in[13];
    const float* a_s0   = (const float*)d_in[14];
    const float* w_s1   = (const float*)d_in[15];
    const float* b_s1   = (const float*)d_in[16];
    const float* a_s1   = (const float*)d_in[17];
    const float* w_s2   = (const float*)d_in[18];
    const float* b_s2   = (const float*)d_in[19];
    const float* a_c0   = (const float*)d_in[20];
    const float* w_c1   = (const float*)d_in[21];
    const float* b_c1   = (const float*)d_in[22];
    const float* a_c1   = (const float*)d_in[23];
    const float* w_c2   = (const float*)d_in[24];
    const float* b_c2   = (const float*)d_in[25];
    const float* a_b0   = (const float*)d_in[26];
    const float* w_b1   = (const float*)d_in[27];
    const float* b_b1   = (const float*)d_in[28];
    const float* a_b1   = (const float*)d_in[29];
    const float* w_b2   = (const float*)d_in[30];
    const float* b_b2   = (const float*)d_in[31];
    float* out = (float*)d_out;

    cudaFuncSetAttribute(band_kernel, cudaFuncAttributeMaxDynamicSharedMemorySize, 183040);
    cudaFuncSetAttribute(dp_kernel,   cudaFuncAttributeMaxDynamicSharedMemorySize, 131072);

    proj_kernel<<<dim3(128, 2), 512>>>(x, IND, 0, wih0f, b0f, wih0b, b0b);
    lstm_kernel<<<16, 256>>>(whh0f, whh0b, 0);
    proj_kernel<<<dim3(128, 2), 512>>>(x, F2D, 1, wih1f, b1f, wih1b, b1b);
    lstm_kernel<<<16, 256>>>(whh1f, whh1b, 1);
    cumsum_kernel<<<2, 256>>>();
    pdpe_kernel<<<512, 128>>>(w_s1, b_s1, a_s0);
    clsbin_kernel<<<512, 160>>>(a_c0, w_c1, b_c1, a_c1, w_c2, b_c2,
                                a_b0, w_b1, b_b1, a_b1, w_b2, b_b2, out);
    band_kernel<<<510, 256, 183040>>>(w_s1, w_s2, b_s2, a_s0, a_s1);
    dp_kernel<<<1, 256, 131072>>>(lens, out);
}